// round 12
// baseline (speedup 1.0000x reference)
#include <cuda_runtime.h>
#include <stdint.h>

#define B_SZ 65536
#define NM 5
#define WPB 8
#define SPW 4                    // samples per warp
#define SPB (WPB * SPW)          // 32 samples per block
#define NBLOCKS (B_SZ / SPB)     // 2048

__device__ float g_partials[NBLOCKS];
__device__ unsigned g_count;     // zero-init; self-resets every launch

__device__ __forceinline__ float sqrt_ap(float x) {
    float r;
    asm("sqrt.approx.f32 %0, %1;" : "=f"(r) : "f"(x));
    return r;
}

// Smooth-L1 (huber, delta=1): ad<1 ? 0.5 d^2 : ad-0.5 == t*(ad - 0.5t), t=min(ad,1)
__device__ __forceinline__ float huber(float d) {
    float ad = fabsf(d);
    float t = fminf(ad, 1.0f);
    return t * fmaf(-0.5f, t, ad);
}

__device__ __forceinline__ uint32_t rotl32(uint32_t x, uint32_t d) {
    return __funnelshift_l(x, x, d);
}

// JAX partitionable ThreeFry-2x32: key=(0,42), counter=(0,i); randint(0,5) -> (x0^x1) % 5
__device__ __forceinline__ int threefry_mod5(uint32_t i) {
    const uint32_t k0 = 0u, k1 = 42u;
    const uint32_t k2 = k0 ^ k1 ^ 0x1BD11BDAu;
    uint32_t x0 = k0;
    uint32_t x1 = i + k1;
#define TF4(r0, r1, r2, r3)                           \
    x0 += x1; x1 = rotl32(x1, r0); x1 ^= x0;          \
    x0 += x1; x1 = rotl32(x1, r1); x1 ^= x0;          \
    x0 += x1; x1 = rotl32(x1, r2); x1 ^= x0;          \
    x0 += x1; x1 = rotl32(x1, r3); x1 ^= x0;
    TF4(13, 15, 26, 6)   x0 += k1; x1 += k2 + 1u;
    TF4(17, 29, 16, 24)  x0 += k2; x1 += k0 + 2u;
    TF4(13, 15, 26, 6)   x0 += k0; x1 += k1 + 3u;
    TF4(17, 29, 16, 24)  x0 += k1; x1 += k2 + 4u;
    TF4(13, 15, 26, 6)   x0 += k2; x1 += k0 + 5u;
#undef TF4
    return (int)((x0 ^ x1) % 5u);
}

__global__ void __launch_bounds__(32 * WPB, 5)
combo_fused(const float* __restrict__ path_pred,
            const float* __restrict__ path_gt,
            const float* __restrict__ cr_pred,
            const float* __restrict__ cr_gt,
            float* __restrict__ out) {
    __shared__ float warp_sums[WPB];
    __shared__ bool  is_last;
    const unsigned FULL = 0xffffffffu;
    const float INF = __int_as_float(0x7f800000);
    const float COS5 = 0.99619469809174553f;
    int lane = threadIdx.x & 31;
    int w = threadIdx.x >> 5;
    int s0 = blockIdx.x * SPB + w * SPW;    // this warp's 4 samples: s0..s0+3

    const float* tp  = path_pred + (size_t)s0 * 505;   // sample j at +j*505
    const float* gtb = path_gt   + (size_t)s0 * 100;   // sample j at +j*100 (400B rows, 16B-aligned)

    int grp = lane >> 3, sub = lane & 7;    // octet grp = sample, sub = mode slot
    bool tl = (lane < 25);                  // traj lanes: lane L owns t=2L, 2L+1

    // ---- batch 1: all unconditional loads, maximal MLP ----
    float4 G[SPW];
    if (tl) {
#pragma unroll
        for (int j = 0; j < SPW; j++)
            G[j] = ((const float4*)(gtb + j * 100))[lane];
    }
    bool eligLane = (sub < NM);
    float ex = 0.f, ey = 0.f, pr = -INF, rfx = 0.f, rfy = 0.f;
    if (eligLane) {                          // lanes 8g+m: eligibility of mode m, sample g
        int o = grp * 505 + sub * 100;
        ex = tp[o + 98]; ey = tp[o + 99];
        pr = tp[grp * 505 + 500 + sub];      // logits
        rfx = gtb[grp * 100 + 98]; rfy = gtb[grp * 100 + 99];   // gt last point
    }
    float crp = 0.f, cry = 0.f;
    if (sub == 0) {                          // BCE inputs on lanes 0,8,16,24
        crp = cr_pred[s0 + grp]; cry = cr_gt[s0 + grp];
    }

    // ---- ThreeFry: one SIMT hash serves all 4 samples (lane&3 selects) ----
    int tfv = threefry_mod5((uint32_t)(s0 + (lane & 3)));
    int rnd[SPW];
#pragma unroll
    for (int j = 0; j < SPW; j++) rnd[j] = __shfl_sync(FULL, tfv, j);

    // ---- batch 2: speculative huber loads for the rand modes (4 samples) ----
    const float* bl = tp + 4 * lane;         // lane's 4-float slice of any traj row
    float sp[SPW][4];
    if (tl) {
#pragma unroll
        for (int j = 0; j < SPW; j++) {
            int o = j * 505 + rnd[j] * 100;
            sp[j][0] = bl[o];     sp[j][1] = bl[o + 1];
            sp[j][2] = bl[o + 2]; sp[j][3] = bl[o + 3];
        }
    }

    // ---- eligibility on split lanes (20 active), one ballot ----
    bool elig = false;
    if (eligLane) {
        float rn = sqrt_ap(fmaf(rfx, rfx, rfy * rfy));
        float tn = sqrt_ap(fmaf(ex, ex, ey * ey));
        float np = rn * tn;
        float dot = fmaf(rfx, ex, rfy * ey);
        bool nanm = isnan(rfx) || isnan(rfy) || isnan(ex) || isnan(ey);
        elig = nanm ? false : (np == 0.f ? true : (dot >= COS5 * np));
    }
    unsigned em = __ballot_sync(FULL, elig);

    // ---- per-sample best + huber partials accumulated into ONE accumulator ----
    float acc = 0.f;                         // sum of huber partials over all 4 samples
    int best[SPW];
#pragma unroll
    for (int j = 0; j < SPW; j++) {
        unsigned emj = (em >> (8 * j)) & 0x1fu;
        float rsj = 0.f;
        if (emj) {                           // heavy path (~13% per sample)
            float bestKey = INF;
            int bj = 0;
#pragma unroll
            for (int m = 0; m < NM; m++) {
                if (emj >> m & 1u) {         // warp-uniform
                    int o = j * 505 + m * 100;
                    float d = 0.f;
                    if (tl) {
                        float dx = bl[o]     - G[j].x, dy = bl[o + 1] - G[j].y;
                        float e2 = bl[o + 2] - G[j].z, f2 = bl[o + 3] - G[j].w;
                        d = sqrt_ap(fmaf(dx, dx, dy * dy)) + sqrt_ap(fmaf(e2, e2, f2 * f2));
                    }
#pragma unroll
                    for (int o2 = 16; o2; o2 >>= 1) d += __shfl_xor_sync(FULL, d, o2);
                    if (d < bestKey) { bestKey = d; bj = m; }   // strict < = first-min
                }
            }
            best[j] = bj;
            int c = j * 505 + bj * 100;      // reload winner row (L1/L2-hot)
            if (tl)
                rsj = huber(bl[c] - G[j].x) + huber(bl[c + 1] - G[j].y)
                    + huber(bl[c + 2] - G[j].z) + huber(bl[c + 3] - G[j].w);
        } else {                             // fast path: speculative regs are the winner
            best[j] = rnd[j];
            if (tl)
                rsj = huber(sp[j][0] - G[j].x) + huber(sp[j][1] - G[j].y)
                    + huber(sp[j][2] - G[j].z) + huber(sp[j][3] - G[j].w);
        }
        acc += rsj;
    }
    // single butterfly reduces all 4 samples' huber sums at once
#pragma unroll
    for (int o = 16; o; o >>= 1) acc += __shfl_xor_sync(FULL, acc, o);

    // ---- log_softmax: octet j reduces sample j's logits (one 3-stage butterfly) ----
    float mx = pr;
#pragma unroll
    for (int o = 4; o; o >>= 1) mx = fmaxf(mx, __shfl_xor_sync(FULL, mx, o));
    float e = eligLane ? __expf(pr - mx) : 0.f;
#pragma unroll
    for (int o = 4; o; o >>= 1) e += __shfl_xor_sync(FULL, e, o);
    float pb0 = __shfl_sync(FULL, pr, best[0]);
    float pb1 = __shfl_sync(FULL, pr, 8 + best[1]);
    float pb2 = __shfl_sync(FULL, pr, 16 + best[2]);
    float pb3 = __shfl_sync(FULL, pr, 24 + best[3]);

    // ---- tail: CE + BCE for sample grp on lanes 0,8,16,24 simultaneously ----
    float contrib = 0.f;
    if (sub == 0) {
        float pb = (grp == 0) ? pb0 : (grp == 1) ? pb1 : (grp == 2) ? pb2 : pb3;
        float ce = (mx + __logf(e)) - pb;
        float lp  = fmaxf(__logf(crp), -100.0f);
        float l1p = fmaxf(log1pf(-crp), -100.0f);
        float bce = -(cry * lp + (1.0f - cry) * l1p);
        contrib = ce + bce;
    }
    contrib += __shfl_xor_sync(FULL, contrib, 8);
    contrib += __shfl_xor_sync(FULL, contrib, 16);

    if (lane == 0) warp_sums[w] = contrib + acc * 0.01f;   // /100 = mean over (50,2)
    __syncthreads();
    if (threadIdx.x == 0) {
        float t = 0.f;
#pragma unroll
        for (int i = 0; i < WPB; i++) t += warp_sums[i];
        g_partials[blockIdx.x] = t;
        __threadfence();
        unsigned done = atomicAdd(&g_count, 1u);
        is_last = (done == NBLOCKS - 1);
    }
    __syncthreads();

    if (is_last) {
        // deterministic finalize: 256 threads, 2 float4 each in fixed order, fixed tree
        __shared__ float sm[32];
        const float4* p4 = (const float4*)g_partials;   // 512 float4, L2-hot
        float4 a = p4[threadIdx.x];
        float4 bq = p4[threadIdx.x + 256];
        float t = ((a.x + a.y) + (a.z + a.w)) + ((bq.x + bq.y) + (bq.z + bq.w));
#pragma unroll
        for (int o = 16; o; o >>= 1) t += __shfl_xor_sync(FULL, t, o);
        if (lane == 0) sm[w] = t;
        __syncthreads();
        if (w == 0) {
            float v = (lane < WPB) ? sm[lane] : 0.f;
#pragma unroll
            for (int o = 4; o; o >>= 1) v += __shfl_xor_sync(FULL, v, o);
            if (lane == 0) {
                out[0] = v * (1.0f / (float)B_SZ);
                g_count = 0;                           // reset for next graph replay
            }
        }
    }
}

extern "C" void kernel_launch(void* const* d_in, const int* in_sizes, int n_in,
                              void* d_out, int out_size) {
    const float* path_pred = (const float*)d_in[0];
    const float* path_gt   = (const float*)d_in[1];
    const float* cr_pred   = (const float*)d_in[2];
    const float* cr_gt     = (const float*)d_in[3];
    // d_in[4] = log_vars (unused by the reference's returned value)
    combo_fused<<<NBLOCKS, 32 * WPB>>>(path_pred, path_gt, cr_pred, cr_gt, (float*)d_out);
}

// round 13
// speedup vs baseline: 1.0014x; 1.0014x over previous
#include <cuda_runtime.h>
#include <stdint.h>

#define B_SZ 65536
#define NM 5
#define WPB 8
#define SPB (WPB * 2)            // 16 samples per block (2 per warp)
#define NBLOCKS (B_SZ / SPB)     // 4096

__device__ float g_partials[NBLOCKS];
__device__ unsigned g_count;     // zero-init; self-resets every launch

__device__ __forceinline__ float sqrt_ap(float x) {
    float r;
    asm("sqrt.approx.f32 %0, %1;" : "=f"(r) : "f"(x));
    return r;
}

// Smooth-L1 (huber, delta=1): ad<1 ? 0.5 d^2 : ad-0.5 == t*(ad - 0.5t), t=min(ad,1)
__device__ __forceinline__ float huber(float d) {
    float ad = fabsf(d);
    float t = fminf(ad, 1.0f);
    return t * fmaf(-0.5f, t, ad);
}

__device__ __forceinline__ uint32_t rotl32(uint32_t x, uint32_t d) {
    return __funnelshift_l(x, x, d);
}

// JAX partitionable ThreeFry-2x32: key=(0,42), counter=(0,i); randint(0,5) -> (x0^x1) % 5
__device__ __forceinline__ int threefry_mod5(uint32_t i) {
    const uint32_t k0 = 0u, k1 = 42u;
    const uint32_t k2 = k0 ^ k1 ^ 0x1BD11BDAu;
    uint32_t x0 = k0;
    uint32_t x1 = i + k1;
#define TF4(r0, r1, r2, r3)                           \
    x0 += x1; x1 = rotl32(x1, r0); x1 ^= x0;          \
    x0 += x1; x1 = rotl32(x1, r1); x1 ^= x0;          \
    x0 += x1; x1 = rotl32(x1, r2); x1 ^= x0;          \
    x0 += x1; x1 = rotl32(x1, r3); x1 ^= x0;
    TF4(13, 15, 26, 6)   x0 += k1; x1 += k2 + 1u;
    TF4(17, 29, 16, 24)  x0 += k2; x1 += k0 + 2u;
    TF4(13, 15, 26, 6)   x0 += k0; x1 += k1 + 3u;
    TF4(17, 29, 16, 24)  x0 += k1; x1 += k2 + 4u;
    TF4(13, 15, 26, 6)   x0 += k2; x1 += k0 + 5u;
#undef TF4
    return (int)((x0 ^ x1) % 5u);
}

// dist-argmin over eligible modes (heavy path, ~13%): lane owns floats 4L..4L+3
__device__ __forceinline__ void heavy_best4(
    const float* __restrict__ bl, int off, float4 G, bool tl,
    unsigned emask, int& best, float& rs) {
    const unsigned FULL = 0xffffffffu;
    const float INF = __int_as_float(0x7f800000);
    float bestKey = INF;
    best = 0;
#pragma unroll
    for (int m = 0; m < NM; m++) {
        if (emask >> m & 1u) {                 // warp-uniform
            int i = off + m * 100;
            float d = 0.f;
            if (tl) {
                float dx = bl[i]     - G.x, dy = bl[i + 1] - G.y;
                float e2 = bl[i + 2] - G.z, f2 = bl[i + 3] - G.w;
                d = sqrt_ap(fmaf(dx, dx, dy * dy)) + sqrt_ap(fmaf(e2, e2, f2 * f2));
            }
#pragma unroll
            for (int o = 16; o; o >>= 1) d += __shfl_xor_sync(FULL, d, o);
            if (d < bestKey) { bestKey = d; best = m; }  // strict < = first-min
        }
    }
    int c = off + best * 100;                  // reload true winner (L1/L2-hot)
    rs = 0.f;
    if (tl)
        rs = huber(bl[c] - G.x) + huber(bl[c + 1] - G.y)
           + huber(bl[c + 2] - G.z) + huber(bl[c + 3] - G.w);
}

__global__ void __launch_bounds__(32 * WPB, 7)
combo_fused(const float* __restrict__ path_pred,
            const float* __restrict__ path_gt,
            const float* __restrict__ cr_pred,
            const float* __restrict__ cr_gt,
            float* __restrict__ out) {
    __shared__ float warp_sums[WPB];
    __shared__ int   s_rand[SPB];
    __shared__ bool  is_last;
    const unsigned FULL = 0xffffffffu;
    const float INF = __int_as_float(0x7f800000);
    const float COS5 = 0.99619469809174553f;
    int lane = threadIdx.x & 31;
    int w = threadIdx.x >> 5;
    int sA = blockIdx.x * SPB + 2 * w;

    const float* tp  = path_pred + (size_t)sA * 505;   // sample A; B at +505
    const float* gtb = path_gt   + (size_t)sA * 100;   // A row; B at +100 (400B rows, 16B-aligned)

    // ---- batch 1: all unconditional loads first, maximal MLP ----
    bool tl = (lane < 25);                     // lane L owns gt/traj points 2L, 2L+1
    float4 GA = make_float4(0.f, 0.f, 0.f, 0.f), GB = GA;
    if (tl) {
        GA = ((const float4*)gtb)[lane];
        GB = ((const float4*)(gtb + 100))[lane];
    }
    bool isB = (lane >= 8);
    int  mlane = lane & 7;                     // mode index within octet
    bool eligLane = (mlane < NM) && (lane < 16);
    float ex = 0.f, ey = 0.f, pr = -INF;
    if (eligLane) {                            // lanes 0..4: A modes, 8..12: B modes
        int base = (isB ? 505 : 0) + mlane * 100 + 98;
        ex = tp[base]; ey = tp[base + 1];
        pr = tp[(isB ? 1005 : 500) + mlane];   // logits
    }
    float crp = 0.f, cry = 0.f;
    if (lane == 0 || lane == 8) {              // BCE inputs: lane0 = A, lane8 = B
        int si = sA + (lane >> 3);
        crp = cr_pred[si]; cry = cr_gt[si];
    }

    // ---- ThreeFry: warp 0 hashes all 16 block samples in one SIMT pass ----
    if (threadIdx.x < SPB)
        s_rand[threadIdx.x] = threefry_mod5((uint32_t)(blockIdx.x * SPB + threadIdx.x));
    __syncthreads();                           // hides under batch-1 DRAM latency
    int rndA = s_rand[2 * w], rndB = s_rand[2 * w + 1];

    // ---- batch 2: speculative huber loads for the rand modes (both samples) ----
    const float* bl = tp + 4 * lane;           // lane's 4-float slice of any traj row
    int iA = rndA * 100;
    int iB = 505 + rndB * 100;
    float spA[4] = {0.f, 0.f, 0.f, 0.f}, spB[4] = {0.f, 0.f, 0.f, 0.f};
    if (tl) {
        spA[0] = bl[iA]; spA[1] = bl[iA + 1]; spA[2] = bl[iA + 2]; spA[3] = bl[iA + 3];
        spB[0] = bl[iB]; spB[1] = bl[iB + 1]; spB[2] = bl[iB + 2]; spB[3] = bl[iB + 3];
    }

    // ref last points (gt point 49 = lane 24's .z/.w) via shfl — no extra LDGs
    float rAx = __shfl_sync(FULL, GA.z, 24), rAy = __shfl_sync(FULL, GA.w, 24);
    float rBx = __shfl_sync(FULL, GB.z, 24), rBy = __shfl_sync(FULL, GB.w, 24);

    // ---- eligibility on split lanes, one ballot ----
    float rfx = isB ? rBx : rAx, rfy = isB ? rBy : rAy;
    bool elig = false;
    if (eligLane) {
        float rn = sqrt_ap(fmaf(rfx, rfx, rfy * rfy));
        float tn = sqrt_ap(fmaf(ex, ex, ey * ey));
        float np = rn * tn;
        float dot = fmaf(rfx, ex, rfy * ey);
        bool nanm = isnan(rfx) || isnan(rfy) || isnan(ex) || isnan(ey);
        elig = nanm ? false : (np == 0.f ? true : (dot >= COS5 * np));
    }
    unsigned em = __ballot_sync(FULL, elig);
    unsigned emA = em & 0x1fu;
    unsigned emB = (em >> 8) & 0x1fu;

    // ---- per-sample best + huber partials into ONE accumulator ----
    int bestA, bestB;
    float acc;
    if (emA) {
        heavy_best4(bl, 0, GA, tl, emA, bestA, acc);
    } else {
        bestA = rndA;
        acc = 0.f;
        if (tl)
            acc = huber(spA[0] - GA.x) + huber(spA[1] - GA.y)
                + huber(spA[2] - GA.z) + huber(spA[3] - GA.w);
    }
    if (emB) {
        float rsB;
        heavy_best4(bl, 505, GB, tl, emB, bestB, rsB);
        acc += rsB;
    } else {
        bestB = rndB;
        if (tl)
            acc += huber(spB[0] - GB.x) + huber(spB[1] - GB.y)
                 + huber(spB[2] - GB.z) + huber(spB[3] - GB.w);
    }
    // single butterfly reduces both samples' huber sums
#pragma unroll
    for (int o = 16; o; o >>= 1) acc += __shfl_xor_sync(FULL, acc, o);

    // ---- log_softmax: octet 0 reduces A logits, octet 1 reduces B ----
    float mx = pr;
#pragma unroll
    for (int o = 4; o; o >>= 1) mx = fmaxf(mx, __shfl_xor_sync(FULL, mx, o));
    float e = eligLane ? __expf(pr - mx) : 0.f;
#pragma unroll
    for (int o = 4; o; o >>= 1) e += __shfl_xor_sync(FULL, e, o);
    float pbA = __shfl_sync(FULL, pr, bestA);        // lanes 0..4 hold A logits
    float pbB = __shfl_sync(FULL, pr, 8 + bestB);    // lanes 8..12 hold B logits

    // ---- tail: CE + BCE on lanes 0 (A) and 8 (B) simultaneously ----
    float contrib = 0.f;
    if (lane == 0 || lane == 8) {
        float pb = isB ? pbB : pbA;
        float ce = (mx + __logf(e)) - pb;
        float lp  = fmaxf(__logf(crp), -100.0f);
        float l1p = fmaxf(log1pf(-crp), -100.0f);
        float bce = -(cry * lp + (1.0f - cry) * l1p);
        contrib = ce + bce;
    }
    float contribB = __shfl_sync(FULL, contrib, 8);

    if (lane == 0) warp_sums[w] = contrib + contribB + acc * 0.01f;  // /100 = mean (50,2)
    __syncthreads();
    if (threadIdx.x == 0) {
        float t = 0.f;
#pragma unroll
        for (int i = 0; i < WPB; i++) t += warp_sums[i];
        g_partials[blockIdx.x] = t;
        __threadfence();
        unsigned done = atomicAdd(&g_count, 1u);
        is_last = (done == NBLOCKS - 1);
    }
    __syncthreads();

    if (is_last) {
        // deterministic finalize: 256 threads, 4 float4 each in fixed order, fixed tree
        __shared__ float sm[32];
        const float4* p4 = (const float4*)g_partials;   // 1024 float4, L2-hot
        float t = 0.f;
#pragma unroll
        for (int i = 0; i < 4; i++) {
            float4 a = p4[threadIdx.x + i * 256];
            t += ((a.x + a.y) + (a.z + a.w));
        }
#pragma unroll
        for (int o = 16; o; o >>= 1) t += __shfl_xor_sync(FULL, t, o);
        if (lane == 0) sm[w] = t;
        __syncthreads();
        if (w == 0) {
            float v = (lane < WPB) ? sm[lane] : 0.f;
#pragma unroll
            for (int o = 4; o; o >>= 1) v += __shfl_xor_sync(FULL, v, o);
            if (lane == 0) {
                out[0] = v * (1.0f / (float)B_SZ);
                g_count = 0;                           // reset for next graph replay
            }
        }
    }
}

extern "C" void kernel_launch(void* const* d_in, const int* in_sizes, int n_in,
                              void* d_out, int out_size) {
    const float* path_pred = (const float*)d_in[0];
    const float* path_gt   = (const float*)d_in[1];
    const float* cr_pred   = (const float*)d_in[2];
    const float* cr_gt     = (const float*)d_in[3];
    // d_in[4] = log_vars (unused by the reference's returned value)
    combo_fused<<<NBLOCKS, 32 * WPB>>>(path_pred, path_gt, cr_pred, cr_gt, (float*)d_out);
}

// round 14
// speedup vs baseline: 1.0111x; 1.0097x over previous
#include <cuda_runtime.h>
#include <stdint.h>

#define B_SZ 65536
#define NM 5
#define WPB 8
#define SPB (WPB * 2)            // 16 samples per block (2 per warp)
#define NBLOCKS (B_SZ / SPB)     // 4096

__device__ float g_partials[NBLOCKS];
__device__ unsigned g_count;     // zero-init; self-resets every launch

__device__ __forceinline__ float sqrt_ap(float x) {
    float r;
    asm("sqrt.approx.f32 %0, %1;" : "=f"(r) : "f"(x));
    return r;
}

// Smooth-L1 (huber, delta=1): ad<1 ? 0.5 d^2 : ad-0.5 == t*(ad - 0.5t), t=min(ad,1)
__device__ __forceinline__ float huber(float d) {
    float ad = fabsf(d);
    float t = fminf(ad, 1.0f);
    return t * fmaf(-0.5f, t, ad);
}

__device__ __forceinline__ uint32_t rotl32(uint32_t x, uint32_t d) {
    return __funnelshift_l(x, x, d);
}

// JAX partitionable ThreeFry-2x32: key=(0,42), counter=(0,i); randint(0,5) -> (x0^x1) % 5
__device__ __forceinline__ int threefry_mod5(uint32_t i) {
    const uint32_t k0 = 0u, k1 = 42u;
    const uint32_t k2 = k0 ^ k1 ^ 0x1BD11BDAu;
    uint32_t x0 = k0;
    uint32_t x1 = i + k1;
#define TF4(r0, r1, r2, r3)                           \
    x0 += x1; x1 = rotl32(x1, r0); x1 ^= x0;          \
    x0 += x1; x1 = rotl32(x1, r1); x1 ^= x0;          \
    x0 += x1; x1 = rotl32(x1, r2); x1 ^= x0;          \
    x0 += x1; x1 = rotl32(x1, r3); x1 ^= x0;
    TF4(13, 15, 26, 6)   x0 += k1; x1 += k2 + 1u;
    TF4(17, 29, 16, 24)  x0 += k2; x1 += k0 + 2u;
    TF4(13, 15, 26, 6)   x0 += k0; x1 += k1 + 3u;
    TF4(17, 29, 16, 24)  x0 += k1; x1 += k2 + 4u;
    TF4(13, 15, 26, 6)   x0 += k2; x1 += k0 + 5u;
#undef TF4
    return (int)((x0 ^ x1) % 5u);
}

// dist-argmin over eligible modes (heavy path, ~13%): lane owns floats 4L..4L+3
__device__ __forceinline__ void heavy_best4(
    const float* __restrict__ bl, int off, float4 G, bool tl,
    unsigned emask, int& best, float& rs) {
    const unsigned FULL = 0xffffffffu;
    const float INF = __int_as_float(0x7f800000);
    float bestKey = INF;
    best = 0;
#pragma unroll
    for (int m = 0; m < NM; m++) {
        if (emask >> m & 1u) {                 // warp-uniform
            int i = off + m * 100;
            float d = 0.f;
            if (tl) {
                float dx = bl[i]     - G.x, dy = bl[i + 1] - G.y;
                float e2 = bl[i + 2] - G.z, f2 = bl[i + 3] - G.w;
                d = sqrt_ap(fmaf(dx, dx, dy * dy)) + sqrt_ap(fmaf(e2, e2, f2 * f2));
            }
#pragma unroll
            for (int o = 16; o; o >>= 1) d += __shfl_xor_sync(FULL, d, o);
            if (d < bestKey) { bestKey = d; best = m; }  // strict < = first-min
        }
    }
    int c = off + best * 100;                  // reload true winner (L1/L2-hot)
    rs = 0.f;
    if (tl)
        rs = huber(bl[c] - G.x) + huber(bl[c + 1] - G.y)
           + huber(bl[c + 2] - G.z) + huber(bl[c + 3] - G.w);
}

__global__ void __launch_bounds__(32 * WPB, 7)
combo_fused(const float* __restrict__ path_pred,
            const float* __restrict__ path_gt,
            const float* __restrict__ cr_pred,
            const float* __restrict__ cr_gt,
            float* __restrict__ out) {
    __shared__ float warp_sums[WPB];
    __shared__ bool  is_last;
    const unsigned FULL = 0xffffffffu;
    const float INF = __int_as_float(0x7f800000);
    const float COS5 = 0.99619469809174553f;
    int lane = threadIdx.x & 31;
    int w = threadIdx.x >> 5;
    int sA = blockIdx.x * SPB + 2 * w;

    const float* tp  = path_pred + (size_t)sA * 505;   // sample A; B at +505
    const float* gtb = path_gt   + (size_t)sA * 100;   // A row; B at +100 (400B rows, 16B-aligned)

    // ---- batch 1: all unconditional loads first, maximal MLP ----
    bool tl = (lane < 25);                     // lane L owns gt/traj points 2L, 2L+1
    float4 GA = make_float4(0.f, 0.f, 0.f, 0.f), GB = GA;
    if (tl) {
        GA = ((const float4*)gtb)[lane];
        GB = ((const float4*)(gtb + 100))[lane];
    }
    bool isB = (lane >= 8);
    int  mlane = lane & 7;                     // mode index within octet
    bool eligLane = (mlane < NM) && (lane < 16);
    float ex = 0.f, ey = 0.f, pr = -INF;
    if (eligLane) {                            // lanes 0..4: A modes, 8..12: B modes
        int base = (isB ? 505 : 0) + mlane * 100 + 98;
        ex = tp[base]; ey = tp[base + 1];
        pr = tp[(isB ? 1005 : 500) + mlane];   // logits
    }
    float crp = 0.f, cry = 0.f;
    if (lane == 0 || lane == 8) {              // BCE inputs: lane0 = A, lane8 = B
        int si = sA + (lane >> 3);
        crp = cr_pred[si]; cry = cr_gt[si];
    }

    // ---- ThreeFry in-warp, NO barrier: hash hides under batch-1 DRAM latency ----
    int tfv = threefry_mod5((uint32_t)(sA + (lane & 1)));
    int rndA = __shfl_sync(FULL, tfv, 0);
    int rndB = __shfl_sync(FULL, tfv, 1);

    // ---- batch 2: speculative huber loads for the rand modes (both samples) ----
    const float* bl = tp + 4 * lane;           // lane's 4-float slice of any traj row
    int iA = rndA * 100;
    int iB = 505 + rndB * 100;
    float spA[4] = {0.f, 0.f, 0.f, 0.f}, spB[4] = {0.f, 0.f, 0.f, 0.f};
    if (tl) {
        spA[0] = bl[iA]; spA[1] = bl[iA + 1]; spA[2] = bl[iA + 2]; spA[3] = bl[iA + 3];
        spB[0] = bl[iB]; spB[1] = bl[iB + 1]; spB[2] = bl[iB + 2]; spB[3] = bl[iB + 3];
    }

    // ref last points (gt point 49 = lane 24's .z/.w) via shfl — no extra LDGs
    float rAx = __shfl_sync(FULL, GA.z, 24), rAy = __shfl_sync(FULL, GA.w, 24);
    float rBx = __shfl_sync(FULL, GB.z, 24), rBy = __shfl_sync(FULL, GB.w, 24);

    // ---- eligibility on split lanes, one ballot ----
    float rfx = isB ? rBx : rAx, rfy = isB ? rBy : rAy;
    bool elig = false;
    if (eligLane) {
        float rn = sqrt_ap(fmaf(rfx, rfx, rfy * rfy));
        float tn = sqrt_ap(fmaf(ex, ex, ey * ey));
        float np = rn * tn;
        float dot = fmaf(rfx, ex, rfy * ey);
        bool nanm = isnan(rfx) || isnan(rfy) || isnan(ex) || isnan(ey);
        elig = nanm ? false : (np == 0.f ? true : (dot >= COS5 * np));
    }
    unsigned em = __ballot_sync(FULL, elig);
    unsigned emA = em & 0x1fu;
    unsigned emB = (em >> 8) & 0x1fu;

    // ---- per-sample best + huber partials into ONE accumulator ----
    int bestA, bestB;
    float acc;
    if (emA) {
        heavy_best4(bl, 0, GA, tl, emA, bestA, acc);
    } else {
        bestA = rndA;
        acc = 0.f;
        if (tl)
            acc = huber(spA[0] - GA.x) + huber(spA[1] - GA.y)
                + huber(spA[2] - GA.z) + huber(spA[3] - GA.w);
    }
    if (emB) {
        float rsB;
        heavy_best4(bl, 505, GB, tl, emB, bestB, rsB);
        acc += rsB;
    } else {
        bestB = rndB;
        if (tl)
            acc += huber(spB[0] - GB.x) + huber(spB[1] - GB.y)
                 + huber(spB[2] - GB.z) + huber(spB[3] - GB.w);
    }
    // single butterfly reduces both samples' huber sums
#pragma unroll
    for (int o = 16; o; o >>= 1) acc += __shfl_xor_sync(FULL, acc, o);

    // ---- log_softmax: octet 0 reduces A logits, octet 1 reduces B ----
    float mx = pr;
#pragma unroll
    for (int o = 4; o; o >>= 1) mx = fmaxf(mx, __shfl_xor_sync(FULL, mx, o));
    float e = eligLane ? __expf(pr - mx) : 0.f;
#pragma unroll
    for (int o = 4; o; o >>= 1) e += __shfl_xor_sync(FULL, e, o);
    float pbA = __shfl_sync(FULL, pr, bestA);        // lanes 0..4 hold A logits
    float pbB = __shfl_sync(FULL, pr, 8 + bestB);    // lanes 8..12 hold B logits

    // ---- tail: CE + BCE on lanes 0 (A) and 8 (B) simultaneously ----
    float contrib = 0.f;
    if (lane == 0 || lane == 8) {
        float pb = isB ? pbB : pbA;
        float ce = (mx + __logf(e)) - pb;
        float lp  = fmaxf(__logf(crp), -100.0f);
        float l1p = fmaxf(log1pf(-crp), -100.0f);
        float bce = -(cry * lp + (1.0f - cry) * l1p);
        contrib = ce + bce;
    }
    float contribB = __shfl_sync(FULL, contrib, 8);

    if (lane == 0) warp_sums[w] = contrib + contribB + acc * 0.01f;  // /100 = mean (50,2)
    __syncthreads();
    if (threadIdx.x == 0) {
        float t = 0.f;
#pragma unroll
        for (int i = 0; i < WPB; i++) t += warp_sums[i];
        g_partials[blockIdx.x] = t;
        __threadfence();
        unsigned done = atomicAdd(&g_count, 1u);
        is_last = (done == NBLOCKS - 1);
    }
    __syncthreads();

    if (is_last) {
        // deterministic finalize: 256 threads, 4 float4 each in fixed order, fixed tree
        __shared__ float sm[32];
        const float4* p4 = (const float4*)g_partials;   // 1024 float4, L2-hot
        float t = 0.f;
#pragma unroll
        for (int i = 0; i < 4; i++) {
            float4 a = p4[threadIdx.x + i * 256];
            t += ((a.x + a.y) + (a.z + a.w));
        }
#pragma unroll
        for (int o = 16; o; o >>= 1) t += __shfl_xor_sync(FULL, t, o);
        if (lane == 0) sm[w] = t;
        __syncthreads();
        if (w == 0) {
            float v = (lane < WPB) ? sm[lane] : 0.f;
#pragma unroll
            for (int o = 4; o; o >>= 1) v += __shfl_xor_sync(FULL, v, o);
            if (lane == 0) {
                out[0] = v * (1.0f / (float)B_SZ);
                g_count = 0;                           // reset for next graph replay
            }
        }
    }
}

extern "C" void kernel_launch(void* const* d_in, const int* in_sizes, int n_in,
                              void* d_out, int out_size) {
    const float* path_pred = (const float*)d_in[0];
    const float* path_gt   = (const float*)d_in[1];
    const float* cr_pred   = (const float*)d_in[2];
    const float* cr_gt     = (const float*)d_in[3];
    // d_in[4] = log_vars (unused by the reference's returned value)
    combo_fused<<<NBLOCKS, 32 * WPB>>>(path_pred, path_gt, cr_pred, cr_gt, (float*)d_out);
}